// round 2
// baseline (speedup 1.0000x reference)
#include <cuda_runtime.h>
#include <math.h>

#define NMAX 40000
#define EMAX 640000
#define DD   128
#define HH   8
#define DKK  16
#define TT   3
#define RR   4
#define NB   16
#define N4   (NMAX * RR)

// ---------------- scratch (device globals) ------------------------------------
__device__ float g_k   [NMAX * DD];           // K projection per node (untransformed)
__device__ float g_v   [NMAX * DD];           // V projection per node (untransformed)
__device__ float g_qt  [NMAX * RR * DD];      // q' = q transformed by Ratt^T per relation
__device__ float g_sp  [NMAX * DD];           // speaker projection per node
__device__ float g_aggr[NMAX * DD];           // normalized+transformed aggregation
__device__ float g_Wsp [DD * DD];             // Vw[1] @ s2u
__device__ float g_bsp [DD];                  // Vb[1] @ s2u
__device__ int   g_win [NMAX];                // winning (max-index) type-0 edge per src
__device__ int   g_thist[N4];                 // histogram per (target, relation)
__device__ int   g_toff [N4 + 1];             // CSR offsets by (target, relation)
__device__ int   g_tcur [N4];                 // scatter cursors
__device__ int   g_epack[EMAX];               // packed src | st<<16, sorted by (tgt,r)
__device__ int   g_bsum [256];                // scan block partials
__device__ int   g_typehist[TT];
__device__ int   g_typecur [TT];
__device__ int   g_perm [NMAX];               // node ids sorted by node type

// ------------------------------- init / histograms ---------------------------
__global__ void k_zero(int n) {
    int i = blockIdx.x * blockDim.x + threadIdx.x;
    if (i < n) g_win[i] = -1;
    if (i < 4 * n) g_thist[i] = 0;
    if (i < TT) g_typehist[i] = 0;
}

__global__ void k_nodehist(const int* __restrict__ ntype, int n) {
    int i = blockIdx.x * blockDim.x + threadIdx.x;
    if (i < n) atomicAdd(&g_typehist[ntype[i]], 1);
}

__global__ void k_edgestats(const int* __restrict__ ei, const int* __restrict__ et, int e) {
    int i = blockIdx.x * blockDim.x + threadIdx.x;
    if (i >= e) return;
    int tgt = ei[e + i];
    int r   = et[i];
    atomicAdd(&g_thist[tgt * RR + r], 1);
    if (r == 0) atomicMax(&g_win[ei[i]], i);   // last (max-index) type-0 edge wins
}

// -------- multi-block exclusive scan of g_thist[0..n4) into g_toff ------------
__global__ void k_scan1(int n4) {
    __shared__ int buf[1024];
    int t = threadIdx.x;
    int gid = blockIdx.x * 1024 + t;
    int v = (gid < n4) ? g_thist[gid] : 0;
    buf[t] = v;
    __syncthreads();
    for (int off = 1; off < 1024; off <<= 1) {
        int x = (t >= off) ? buf[t - off] : 0;
        __syncthreads();
        buf[t] += x;
        __syncthreads();
    }
    if (gid < n4) g_toff[gid] = buf[t] - v;
    if (t == 1023) g_bsum[blockIdx.x] = buf[t];
}

__global__ void k_scan2(int nblocks, int n4) {
    if (threadIdx.x == 0) {
        int run = 0;
        for (int b = 0; b < nblocks; b++) { int x = g_bsum[b]; g_bsum[b] = run; run += x; }
        g_toff[n4] = run;
        int o = 0;
        for (int ty = 0; ty < TT; ty++) { g_typecur[ty] = o; o += g_typehist[ty]; }
    }
}

__global__ void k_scan3(int n4) {
    int gid = blockIdx.x * blockDim.x + threadIdx.x;
    if (gid < n4) {
        int v = g_toff[gid] + g_bsum[gid >> 10];
        g_toff[gid] = v;
        g_tcur[gid] = v;
    }
}

__global__ void k_scatter_edges(const int* __restrict__ ei, const int* __restrict__ et,
                                const int* __restrict__ ntype, int e) {
    int i = blockIdx.x * blockDim.x + threadIdx.x;
    if (i >= e) return;
    int src = ei[i];
    int tgt = ei[e + i];
    int r   = et[i];
    int st  = ntype[src];
    int pos = atomicAdd(&g_tcur[tgt * RR + r], 1);
    g_epack[pos] = src | (st << 16);
}

__global__ void k_scatter_nodes(const int* __restrict__ ntype, int n) {
    int i = blockIdx.x * blockDim.x + threadIdx.x;
    if (i >= n) return;
    int pos = atomicAdd(&g_typecur[ntype[i]], 1);
    g_perm[pos] = i;
}

// ------------------------- Wsp = Vw[1] @ s2u ; bsp = Vb[1] @ s2u --------------
__global__ void k_wsp(const float* __restrict__ Vw, const float* __restrict__ Vb,
                      const float* __restrict__ s2u) {
    int b = blockIdx.x;
    int d = threadIdx.x;
    float acc = 0.f;
    if (b < DD) {
        for (int m = 0; m < DD; m++)
            acc += Vw[(DD + b) * DD + m] * s2u[m * DD + d];
        g_Wsp[b * DD + d] = acc;
    } else {
        for (int m = 0; m < DD; m++)
            acc += Vb[DD + m] * s2u[m * DD + d];
        g_bsp[d] = acc;
    }
}

// ----- projections (K,Q,V,speaker) + per-relation Q transforms, fused ---------
__global__ void __launch_bounds__(256)
k_proj(const float* __restrict__ x, const int* __restrict__ ntype,
       const float* __restrict__ Kw, const float* __restrict__ Kb,
       const float* __restrict__ Qw, const float* __restrict__ Qb,
       const float* __restrict__ Vw, const float* __restrict__ Vb,
       const float* __restrict__ Ratt, int n) {
    __shared__ float xs[NB][DD];
    __shared__ float qs[NB][DD];
    __shared__ int nodes_s[NB], types_s[NB];
    int tid = threadIdx.x;
    int g = tid >> 7;          // node-group 0/1 (8 nodes each)
    int d = tid & 127;
    int base = blockIdx.x * NB;
    if (tid < NB) {
        int idx = base + tid;
        int nd = (idx < n) ? g_perm[idx] : -1;
        nodes_s[tid] = nd;
        types_s[tid] = (nd >= 0) ? ntype[nd] : 0;
    }
    __syncthreads();
    int nodes[8], tj[8];
#pragma unroll
    for (int j = 0; j < 8; j++) { nodes[j] = nodes_s[g * 8 + j]; tj[j] = types_s[g * 8 + j]; }
#pragma unroll
    for (int j = 0; j < 8; j++)
        xs[g * 8 + j][d] = (nodes[j] >= 0) ? x[nodes[j] * DD + d] : 0.f;
    __syncthreads();

    int tmin = tj[0], tmax = tj[0];
#pragma unroll
    for (int j = 1; j < 8; j++) { tmin = min(tmin, tj[j]); tmax = max(tmax, tj[j]); }

    float aK[8], aQ[8], aV[8], aS[8];
#pragma unroll
    for (int j = 0; j < 8; j++) {
        aK[j] = Kb[tj[j] * DD + d];
        aQ[j] = Qb[tj[j] * DD + d];
        aV[j] = Vb[tj[j] * DD + d];
        aS[j] = g_bsp[d];
    }

    if (tmin == tmax) {
        int t = tmin;
#pragma unroll 4
        for (int k = 0; k < DD; k++) {
            float ws = g_Wsp[k * DD + d];
            float wk = Kw[(t * DD + k) * DD + d];
            float wq = Qw[(t * DD + k) * DD + d];
            float wv = Vw[(t * DD + k) * DD + d];
            float xv[8];
#pragma unroll
            for (int j = 0; j < 8; j++) xv[j] = xs[g * 8 + j][k];
#pragma unroll
            for (int j = 0; j < 8; j++) {
                aS[j] += xv[j] * ws;
                aK[j] += xv[j] * wk;
                aQ[j] += xv[j] * wq;
                aV[j] += xv[j] * wv;
            }
        }
    } else {
#pragma unroll 2
        for (int k = 0; k < DD; k++) {
            float ws = g_Wsp[k * DD + d];
            float xv[8];
#pragma unroll
            for (int j = 0; j < 8; j++) xv[j] = xs[g * 8 + j][k];
#pragma unroll
            for (int j = 0; j < 8; j++) aS[j] += xv[j] * ws;
            for (int t = tmin; t <= tmax; t++) {
                float wk = Kw[(t * DD + k) * DD + d];
                float wq = Qw[(t * DD + k) * DD + d];
                float wv = Vw[(t * DD + k) * DD + d];
#pragma unroll
                for (int j = 0; j < 8; j++) {
                    if (tj[j] == t) {
                        aK[j] += xv[j] * wk;
                        aQ[j] += xv[j] * wq;
                        aV[j] += xv[j] * wv;
                    }
                }
            }
        }
    }

#pragma unroll
    for (int j = 0; j < 8; j++) {
        if (nodes[j] >= 0) {
            g_k [nodes[j] * DD + d] = aK[j];
            g_v [nodes[j] * DD + d] = aV[j];
            g_sp[nodes[j] * DD + d] = aS[j];
        }
        qs[g * 8 + j][d] = aQ[j];
    }
    __syncthreads();

    // q' per relation: qt(h,dk) = sum_f q(h,f) * Ratt[r,h,dk,f]
    int h = d >> 4, dk = d & 15;
    for (int r = 0; r < RR; r++) {
        float ar[DKK];
#pragma unroll
        for (int f = 0; f < DKK; f++)
            ar[f] = Ratt[((r * HH + h) * DKK + dk) * DKK + f];
#pragma unroll
        for (int j = 0; j < 8; j++) {
            if (nodes[j] < 0) continue;
            float qt = 0.f;
#pragma unroll
            for (int f = 0; f < DKK; f++)
                qt += qs[g * 8 + j][(h << 4) + f] * ar[f];
            g_qt[(nodes[j] * RR + r) * DD + d] = qt;
        }
    }
}

// ------- attention: warp per target, per-relation sub-loops, no softmax-max ---
__global__ void __launch_bounds__(256)
k_attn(const int* __restrict__ ntype, const float* __restrict__ pri,
       const float* __restrict__ Rmsg, int n) {
    __shared__ float accsh[8][RR][DD];   // 16 KB
    int warp = threadIdx.x >> 5, lane = threadIdx.x & 31;
    int i = blockIdx.x * 8 + warp;
    if (i >= n) return;
    int d0 = lane * 4;
    int h  = lane >> 2;

    int tt = ntype[i];
    float p0[TT], p1[TT], p2[TT], p3[TT];
#pragma unroll
    for (int st = 0; st < TT; st++) {
        p0[st] = pri[((tt * RR + 0) * TT + st) * HH + h];
        p1[st] = pri[((tt * RR + 1) * TT + st) * HH + h];
        p2[st] = pri[((tt * RR + 2) * TT + st) * HH + h];
        p3[st] = pri[((tt * RR + 3) * TT + st) * HH + h];
    }

    float den = 0.f;
    float4 acc[RR];
#pragma unroll
    for (int r = 0; r < RR; r++) acc[r] = make_float4(0.f, 0.f, 0.f, 0.f);

#pragma unroll
    for (int r = 0; r < RR; r++) {
        int beg = g_toff[i * RR + r], end = g_toff[i * RR + r + 1];
        if (beg == end) continue;
        float4 qtr = *(const float4*)&g_qt[(i * RR + r) * DD + d0];
        float4 a = make_float4(0.f, 0.f, 0.f, 0.f);
        for (int idx = beg; idx < end; idx++) {
            int pk  = g_epack[idx];
            int src = pk & 0xFFFF;
            int st  = pk >> 16;
            const float4 k4 = *(const float4*)&g_k[src * DD + d0];
            float s = qtr.x * k4.x + qtr.y * k4.y + qtr.z * k4.z + qtr.w * k4.w;
            s += __shfl_xor_sync(0xffffffffu, s, 1);
            s += __shfl_xor_sync(0xffffffffu, s, 2);
            float pr = (r == 0) ? p0[0] : (r == 1) ? p1[0] : (r == 2) ? p2[0] : p3[0];
            if (st == 1) pr = (r == 0) ? p0[1] : (r == 1) ? p1[1] : (r == 2) ? p2[1] : p3[1];
            if (st == 2) pr = (r == 0) ? p0[2] : (r == 1) ? p1[2] : (r == 2) ? p2[2] : p3[2];
            float pe = __expf(s * pr * 0.25f);
            den += pe;
            const float4 v4 = *(const float4*)&g_v[src * DD + d0];
            a.x += pe * v4.x;
            a.y += pe * v4.y;
            a.z += pe * v4.z;
            a.w += pe * v4.w;
        }
        acc[r] = a;
    }

    float inv = 1.f / (den + 1e-16f);
#pragma unroll
    for (int r = 0; r < RR; r++) {
        accsh[warp][r][d0 + 0] = acc[r].x * inv;
        accsh[warp][r][d0 + 1] = acc[r].y * inv;
        accsh[warp][r][d0 + 2] = acc[r].z * inv;
        accsh[warp][r][d0 + 3] = acc[r].w * inv;
    }
    __syncwarp();

    // out(h,f) = sum_r sum_dk acc_r(h,dk) * Rmsg[r,h,dk,f]
    int f0 = (lane & 3) * 4;   // this lane's 4 f-values, head h
    float4 o = make_float4(0.f, 0.f, 0.f, 0.f);
#pragma unroll
    for (int r = 0; r < RR; r++) {
#pragma unroll 4
        for (int dk = 0; dk < DKK; dk++) {
            float a = accsh[warp][r][(h << 4) + dk];
            const float4 w = *(const float4*)&Rmsg[(((r * HH + h) * DKK + dk) * DKK) + f0];
            o.x += a * w.x;
            o.y += a * w.y;
            o.z += a * w.z;
            o.w += a * w.w;
        }
    }
    *(float4*)&g_aggr[i * DD + d0] = o;
}

// ------------- final: speaker add + GELU + per-type A projection + skip -------
__global__ void __launch_bounds__(256)
k_final(const float* __restrict__ x, const int* __restrict__ ntype,
        const int* __restrict__ ei,
        const float* __restrict__ Aw, const float* __restrict__ Ab,
        const float* __restrict__ skip, float* __restrict__ out, int n, int e) {
    __shared__ float gs[NB][DD];
    __shared__ int nodes_s[NB], types_s[NB];
    int tid = threadIdx.x;
    int g = tid >> 7;
    int d = tid & 127;
    int base = blockIdx.x * NB;
    if (tid < NB) {
        int idx = base + tid;
        int nd = (idx < n) ? g_perm[idx] : -1;
        nodes_s[tid] = nd;
        types_s[tid] = (nd >= 0) ? ntype[nd] : 0;
    }
    __syncthreads();
    int nodes[8], tj[8];
#pragma unroll
    for (int j = 0; j < 8; j++) { nodes[j] = nodes_s[g * 8 + j]; tj[j] = types_s[g * 8 + j]; }

#pragma unroll
    for (int j = 0; j < 8; j++) {
        float v = 0.f;
        if (nodes[j] >= 0) {
            v = g_aggr[nodes[j] * DD + d];
            int we = g_win[nodes[j]];
            if (we >= 0) {
                int tg = ei[e + we];
                v += g_sp[tg * DD + d];
            }
            v = 0.5f * v * (1.f + erff(v * 0.70710678118654752f));
        }
        gs[g * 8 + j][d] = v;
    }
    __syncthreads();

    int tmin = tj[0], tmax = tj[0];
#pragma unroll
    for (int j = 1; j < 8; j++) { tmin = min(tmin, tj[j]); tmax = max(tmax, tj[j]); }

    float aA[8];
#pragma unroll
    for (int j = 0; j < 8; j++) aA[j] = Ab[tj[j] * DD + d];

    if (tmin == tmax) {
        int t = tmin;
#pragma unroll 4
        for (int k = 0; k < DD; k++) {
            float w = Aw[(t * DD + k) * DD + d];
            float xv[8];
#pragma unroll
            for (int j = 0; j < 8; j++) xv[j] = gs[g * 8 + j][k];
#pragma unroll
            for (int j = 0; j < 8; j++) aA[j] += xv[j] * w;
        }
    } else {
#pragma unroll 2
        for (int k = 0; k < DD; k++) {
            float xv[8];
#pragma unroll
            for (int j = 0; j < 8; j++) xv[j] = gs[g * 8 + j][k];
            for (int t = tmin; t <= tmax; t++) {
                float w = Aw[(t * DD + k) * DD + d];
#pragma unroll
                for (int j = 0; j < 8; j++)
                    if (tj[j] == t) aA[j] += xv[j] * w;
            }
        }
    }

#pragma unroll
    for (int j = 0; j < 8; j++) {
        if (nodes[j] < 0) continue;
        float sk = skip[tj[j]];
        float alpha = 1.f / (1.f + __expf(-sk));
        out[nodes[j] * DD + d] = aA[j] * alpha + x[nodes[j] * DD + d] * (1.f - alpha);
    }
}

// --------------------------------- launcher -----------------------------------
extern "C" void kernel_launch(void* const* d_in, const int* in_sizes, int n_in,
                              void* d_out, int out_size) {
    const float* node_inp  = (const float*)d_in[0];
    const int*   node_type = (const int*)  d_in[1];
    const int*   edge_index= (const int*)  d_in[2];
    const int*   edge_type = (const int*)  d_in[3];
    const float* Kw = (const float*)d_in[5];
    const float* Kb = (const float*)d_in[6];
    const float* Qw = (const float*)d_in[7];
    const float* Qb = (const float*)d_in[8];
    const float* Vw = (const float*)d_in[9];
    const float* Vb = (const float*)d_in[10];
    const float* Aw = (const float*)d_in[11];
    const float* Ab = (const float*)d_in[12];
    const float* pri  = (const float*)d_in[13];
    const float* Ratt = (const float*)d_in[14];
    const float* Rmsg = (const float*)d_in[15];
    const float* s2u  = (const float*)d_in[16];
    const float* skip = (const float*)d_in[17];
    float* out = (float*)d_out;

    int n = in_sizes[1];
    int e = in_sizes[3];
    if (n > NMAX) n = NMAX;
    if (e > EMAX) e = EMAX;
    int n4 = n * RR;

    int nb  = (n + 255) / 256;
    int n4b = (n4 + 255) / 256;
    int eb  = (e + 255) / 256;
    int sb  = (n4 + 1023) / 1024;   // scan blocks (<= 157 <= 256)

    k_zero<<<n4b, 256>>>(n);
    k_nodehist<<<nb, 256>>>(node_type, n);
    k_edgestats<<<eb, 256>>>(edge_index, edge_type, e);
    k_scan1<<<sb, 1024>>>(n4);
    k_scan2<<<1, 32>>>(sb, n4);
    k_scan3<<<n4b, 256>>>(n4);
    k_scatter_edges<<<eb, 256>>>(edge_index, edge_type, node_type, e);
    k_scatter_nodes<<<nb, 256>>>(node_type, n);
    k_wsp<<<DD + 1, DD>>>(Vw, Vb, s2u);
    k_proj<<<(n + NB - 1) / NB, 256>>>(node_inp, node_type, Kw, Kb, Qw, Qb, Vw, Vb,
                                       Ratt, n);
    k_attn<<<(n + 7) / 8, 256>>>(node_type, pri, Rmsg, n);
    k_final<<<(n + NB - 1) / NB, 256>>>(node_inp, node_type, edge_index, Aw, Ab,
                                        skip, out, n, e);
}